// round 16
// baseline (speedup 1.0000x reference)
#include <cuda_runtime.h>
#include <cuda_fp16.h>
#include <math.h>

// Problem constants
#define D    512
#define BB   64
#define TSRC 48
#define TTGT 48
#define VDE  32000
#define S    (BB * D)        // 32768 = one (B,D) state
#define M3   (TSRC * BB)     // 3072 rows

// recurrence partition: 4 b-groups x 32 j-groups = 128 CTAs
#define NGB 4
#define NGJ 32
#define NB  16
#define NJ  16
#define RSTR 516
#define RS  (NB * RSTR)

// ---------------- scratch (device globals) -----------------------------------
__device__ float g_Wcat[1536 * D];
__device__ float g_bcat[1536];
__device__ float g_Ut[D * D];
__device__ float g_G[2 * M3 * 1536];     // [Genc ; Gdec] contiguous
__device__ float g_h1[2 * S];
__device__ float g_h2[2 * S];
__device__ float g_H[TSRC * S];
__device__ float g_hall[TTGT * S];
__device__ float g_ctx[TTGT * S];
__device__ __half g_Wout16[VDE * D];     // fp16 copy of W_out
__device__ __half g_A16[M3 * D];         // fp16 out = hall + ctx@Wctx^T
__device__ unsigned g_flags[NGB * NGJ * 32];  // one 128B line per flag

// ---------------------------------------------------------------------------
__device__ __forceinline__ unsigned f2tf32(float x) {
    unsigned r;
    asm("cvt.rna.tf32.f32 %0, %1;" : "=r"(r) : "f"(x));
    return r;
}

__device__ __forceinline__ void cpasync16(void* sptr, const void* gptr) {
    unsigned s = (unsigned)__cvta_generic_to_shared(sptr);
    asm volatile("cp.async.ca.shared.global [%0], [%1], 16;" :: "r"(s), "l"(gptr));
}
// L2-coherent 16B async copy (bypasses L1; required for cross-SM staging)
__device__ __forceinline__ void cpacg16(void* sptr, const void* gptr) {
    unsigned s = (unsigned)__cvta_generic_to_shared(sptr);
    asm volatile("cp.async.cg.shared.global [%0], [%1], 16;" :: "r"(s), "l"(gptr));
}

// packed fp32x2 FMA (Blackwell) + paired smem loads (proven R9/R11)
#define LDSV2(p, lo, hi) do {                                                \
    unsigned _a = (unsigned)__cvta_generic_to_shared((const void*)(p));      \
    asm volatile("ld.shared.v2.u64 {%0,%1}, [%2];"                           \
                 : "=l"(lo), "=l"(hi) : "r"(_a)); } while (0)
#define FMA2(acc, a, b)                                                      \
    asm volatile("fma.rn.f32x2 %0, %1, %2, %0;" : "+l"(acc) : "l"(a), "l"(b))

__device__ __forceinline__ float rsum2(unsigned long long a, unsigned long long b) {
    float x0, x1, y0, y1;
    asm("mov.b64 {%0,%1}, %2;" : "=f"(x0), "=f"(x1) : "l"(a));
    asm("mov.b64 {%0,%1}, %2;" : "=f"(y0), "=f"(y1) : "l"(b));
    return (x0 + x1) + (y0 + y1);
}

// ---------------------------------------------------------------------------
// Generic tf32 NT GEMM (proven). Split id space for fused enc+dec gate GEMM.
// C16 != nullptr: write fp16 output instead of fp32 (feeds logits GEMM).
// ---------------------------------------------------------------------------
__global__ __launch_bounds__(256) void sgemm_tf32(
    const float* __restrict__ A, const int* __restrict__ ids,
    const float* __restrict__ E, const int* __restrict__ ids2,
    const float* __restrict__ E2, int Msplit,
    const float* __restrict__ Bm,
    const float* __restrict__ bias, const float* __restrict__ addend,
    float* __restrict__ C, __half* __restrict__ C16, int M, int N, int K)
{
    __shared__ unsigned As[128 * 36];
    __shared__ unsigned Bs[128 * 36];

    const int tid  = threadIdx.x;
    const int lane = tid & 31;
    const int warp = tid >> 5;
    const int row0 = blockIdx.y * 128;
    const int col0 = blockIdx.x * 128;

    const int mwarp = (warp >> 2) * 64;
    const int nwarp = (warp & 3) * 32;
    const int gid = lane >> 2;
    const int tig = lane & 3;

    const int lr = tid >> 3;
    const int lc = (tid & 7) * 4;

    const float* aPtr[4];
    const float* bPtr[4];
#pragma unroll
    for (int i = 0; i < 4; i++) {
        int r = row0 + lr + 32 * i;
        if (ids) {
            if (ids2 && r >= Msplit) aPtr[i] = E2 + (size_t)ids2[r - Msplit] * K;
            else                     aPtr[i] = E + (size_t)ids[r] * K;
        } else {
            aPtr[i] = A + (size_t)r * K;
        }
        bPtr[i] = Bm + (size_t)(col0 + lr + 32 * i) * K;
    }

    float acc[4][4][4];
#pragma unroll
    for (int mt = 0; mt < 4; mt++)
#pragma unroll
        for (int nt = 0; nt < 4; nt++)
#pragma unroll
            for (int q = 0; q < 4; q++) acc[mt][nt][q] = 0.f;

    const int kchunks = K >> 5;
    float4 aReg[4], bReg[4];
#pragma unroll
    for (int i = 0; i < 4; i++) {
        aReg[i] = *(const float4*)(aPtr[i] + lc);
        bReg[i] = *(const float4*)(bPtr[i] + lc);
    }

    for (int ch = 0; ch < kchunks; ch++) {
#pragma unroll
        for (int i = 0; i < 4; i++) {
            int base = (lr + 32 * i) * 36 + lc;
            uint4 av, bv;
            av.x = f2tf32(aReg[i].x); av.y = f2tf32(aReg[i].y);
            av.z = f2tf32(aReg[i].z); av.w = f2tf32(aReg[i].w);
            bv.x = f2tf32(bReg[i].x); bv.y = f2tf32(bReg[i].y);
            bv.z = f2tf32(bReg[i].z); bv.w = f2tf32(bReg[i].w);
            *(uint4*)&As[base] = av;
            *(uint4*)&Bs[base] = bv;
        }
        __syncthreads();

        if (ch + 1 < kchunks) {
            int koff = (ch + 1) * 32 + lc;
#pragma unroll
            for (int i = 0; i < 4; i++) {
                aReg[i] = *(const float4*)(aPtr[i] + koff);
                bReg[i] = *(const float4*)(bPtr[i] + koff);
            }
        }

#pragma unroll
        for (int ks = 0; ks < 4; ks++) {
            int k0 = ks * 8;
            unsigned bf[4][2];
#pragma unroll
            for (int nt = 0; nt < 4; nt++) {
                int nb = nwarp + nt * 8 + gid;
                bf[nt][0] = Bs[nb * 36 + k0 + tig];
                bf[nt][1] = Bs[nb * 36 + k0 + tig + 4];
            }
#pragma unroll
            for (int mt = 0; mt < 4; mt++) {
                int rm = mwarp + mt * 16 + gid;
                unsigned a0 = As[rm * 36 + k0 + tig];
                unsigned a1 = As[(rm + 8) * 36 + k0 + tig];
                unsigned a2 = As[rm * 36 + k0 + tig + 4];
                unsigned a3 = As[(rm + 8) * 36 + k0 + tig + 4];
#pragma unroll
                for (int nt = 0; nt < 4; nt++) {
                    asm volatile(
                        "mma.sync.aligned.m16n8k8.row.col.f32.tf32.tf32.f32 "
                        "{%0,%1,%2,%3}, {%4,%5,%6,%7}, {%8,%9}, {%0,%1,%2,%3};"
                        : "+f"(acc[mt][nt][0]), "+f"(acc[mt][nt][1]),
                          "+f"(acc[mt][nt][2]), "+f"(acc[mt][nt][3])
                        : "r"(a0), "r"(a1), "r"(a2), "r"(a3),
                          "r"(bf[nt][0]), "r"(bf[nt][1]));
                }
            }
        }
        __syncthreads();
    }

#pragma unroll
    for (int mt = 0; mt < 4; mt++) {
        int r = row0 + mwarp + mt * 16 + gid;
#pragma unroll
        for (int nt = 0; nt < 4; nt++) {
            int c = col0 + nwarp + nt * 8 + tig * 2;
            float v0 = acc[mt][nt][0], v1 = acc[mt][nt][1];
            float v2 = acc[mt][nt][2], v3 = acc[mt][nt][3];
            if (bias) {
                float b0 = bias[c], b1 = bias[c + 1];
                v0 += b0; v1 += b1; v2 += b0; v3 += b1;
            }
            if (addend) {
                float2 a0 = *(const float2*)&addend[(size_t)r * N + c];
                float2 a1 = *(const float2*)&addend[(size_t)(r + 8) * N + c];
                v0 += a0.x; v1 += a0.y; v2 += a1.x; v3 += a1.y;
            }
            if (C16) {
                *(__half2*)&C16[(size_t)r * N + c] = __floats2half2_rn(v0, v1);
                *(__half2*)&C16[(size_t)(r + 8) * N + c] = __floats2half2_rn(v2, v3);
            } else {
                float2 o0; o0.x = v0; o0.y = v1;
                float2 o1; o1.x = v2; o1.y = v3;
                *(float2*)&C[(size_t)r * N + c] = o0;
                *(float2*)&C[(size_t)(r + 8) * N + c] = o1;
            }
        }
    }
}

// ---------------------------------------------------------------------------
// Logits GEMM fp16 (R11, proven): BM=128, BN=128, BK=32 halfs, 256 threads,
// 3-stage cp.async, 2 CTAs/SM.
// ---------------------------------------------------------------------------
#define SAW 20                 // smem row stride in 32-bit words
#define STW (128 * SAW)        // words per matrix per stage (2560)

__global__ __launch_bounds__(256, 2) void gemm_logits16(
    const __half* __restrict__ A, const __half* __restrict__ B,
    float* __restrict__ C)
{
    extern __shared__ unsigned smL[];
    unsigned* AsW = smL;             // [3][STW]
    unsigned* BsW = smL + 3 * STW;   // [3][STW]

    const int tid  = threadIdx.x;
    const int lane = tid & 31;
    const int warp = tid >> 5;       // 0..7
    const int row0 = blockIdx.y * 128;
    const int col0 = blockIdx.x * 128;

    const int mwarp = (warp >> 2) * 64;   // 0,64
    const int nwarp = (warp & 3) * 32;    // 0,32,64,96
    const int gid = lane >> 2;
    const int tig = lane & 3;

    const int rL = tid >> 1;
    const int hL = (tid & 1) * 16;            // halfs
    const __half* gA = A + (size_t)(row0 + rL) * D + hL;
    const __half* gB = B + (size_t)(col0 + rL) * D + hL;
    unsigned* dA = AsW + rL * SAW + (tid & 1) * 8;
    unsigned* dB = BsW + rL * SAW + (tid & 1) * 8;

#define LISSUE(ch, buf)                                                     \
    do {                                                                    \
        int ko = (ch) * 32;                                                 \
        cpasync16(dA + (buf) * STW + 0, gA + ko + 0);                       \
        cpasync16(dA + (buf) * STW + 4, gA + ko + 8);                       \
        cpasync16(dB + (buf) * STW + 0, gB + ko + 0);                       \
        cpasync16(dB + (buf) * STW + 4, gB + ko + 8);                       \
        asm volatile("cp.async.commit_group;");                             \
    } while (0)

    float acc[4][4][4];
#pragma unroll
    for (int mt = 0; mt < 4; mt++)
#pragma unroll
        for (int nt = 0; nt < 4; nt++)
#pragma unroll
            for (int q = 0; q < 4; q++) acc[mt][nt][q] = 0.f;

    LISSUE(0, 0);
    LISSUE(1, 1);
    LISSUE(2, 2);

    const int NCH = D / 32;   // 16
    for (int ch = 0; ch < NCH; ch++) {
        if      (ch <= NCH - 3) asm volatile("cp.async.wait_group 2;");
        else if (ch == NCH - 2) asm volatile("cp.async.wait_group 1;");
        else                    asm volatile("cp.async.wait_group 0;");
        __syncthreads();

        const int buf = ch % 3;
        const unsigned* Af = AsW + buf * STW;
        const unsigned* Bf = BsW + buf * STW;
#pragma unroll
        for (int ks = 0; ks < 2; ks++) {
            int kb = ks * 8;
            unsigned bf[4][2];
#pragma unroll
            for (int nt = 0; nt < 4; nt++) {
                int nb = nwarp + nt * 8 + gid;
                bf[nt][0] = Bf[nb * SAW + kb + tig];
                bf[nt][1] = Bf[nb * SAW + kb + tig + 4];
            }
#pragma unroll
            for (int mt = 0; mt < 4; mt++) {
                int rm = mwarp + mt * 16 + gid;
                unsigned a0 = Af[rm * SAW + kb + tig];
                unsigned a1 = Af[(rm + 8) * SAW + kb + tig];
                unsigned a2 = Af[rm * SAW + kb + tig + 4];
                unsigned a3 = Af[(rm + 8) * SAW + kb + tig + 4];
#pragma unroll
                for (int nt = 0; nt < 4; nt++) {
                    asm volatile(
                        "mma.sync.aligned.m16n8k16.row.col.f32.f16.f16.f32 "
                        "{%0,%1,%2,%3}, {%4,%5,%6,%7}, {%8,%9}, {%0,%1,%2,%3};"
                        : "+f"(acc[mt][nt][0]), "+f"(acc[mt][nt][1]),
                          "+f"(acc[mt][nt][2]), "+f"(acc[mt][nt][3])
                        : "r"(a0), "r"(a1), "r"(a2), "r"(a3),
                          "r"(bf[nt][0]), "r"(bf[nt][1]));
                }
            }
        }
        __syncthreads();
        if (ch + 3 < NCH) LISSUE(ch + 3, buf);
    }
#undef LISSUE

#pragma unroll
    for (int mt = 0; mt < 4; mt++) {
        size_t rr = (size_t)(row0 + mwarp + mt * 16 + gid);
#pragma unroll
        for (int nt = 0; nt < 4; nt++) {
            int c = col0 + nwarp + nt * 8 + tig * 2;
            float2 o0; o0.x = acc[mt][nt][0]; o0.y = acc[mt][nt][1];
            float2 o1; o1.x = acc[mt][nt][2]; o1.y = acc[mt][nt][3];
            *(float2*)&C[rr * VDE + c] = o0;
            *(float2*)&C[(rr + 8) * VDE + c] = o1;
        }
    }
}

// ---------------------------------------------------------------------------
__global__ void build_wcat(const float* __restrict__ Wz, const float* __restrict__ bz,
                           const float* __restrict__ Wr, const float* __restrict__ br,
                           const float* __restrict__ Wn, const float* __restrict__ bn)
{
    int idx = blockIdx.x * blockDim.x + threadIdx.x;
    if (idx >= 1536 * D) return;
    int j = idx / D, k = idx % D;
    int g = j >> 9, jr = j & 511;
    const float* W = (g == 0) ? Wz : (g == 1) ? Wr : Wn;
    g_Wcat[idx] = W[jr * D + k];
    if (k == 0) {
        const float* bvec = (g == 0) ? bz : (g == 1) ? br : bn;
        g_bcat[j] = bvec[jr];
    }
}

// transpose U + zero state + clear (padded) flags
__global__ void prep(const float* __restrict__ U, float* __restrict__ Ut,
                     float* __restrict__ h1, float* __restrict__ h2,
                     unsigned* __restrict__ flags)
{
    __shared__ float tile[32][33];
    int k0 = blockIdx.y * 32;
    int j0 = blockIdx.x * 32;
    int tx = threadIdx.x, ty = threadIdx.y;
#pragma unroll
    for (int i = 0; i < 4; i++)
        tile[ty + i * 8][tx] = U[(size_t)(k0 + ty + i * 8) * D + j0 + tx];
    __syncthreads();
#pragma unroll
    for (int i = 0; i < 4; i++)
        Ut[(size_t)(j0 + ty + i * 8) * D + k0 + tx] = tile[tx][ty + i * 8];

    int bid = blockIdx.y * 16 + blockIdx.x;   // 0..255
    int t   = ty * 32 + tx;                   // 0..255
    if (t < 128) {
        int base = bid * 128 + t;
        h1[base] = 0.f;
        h2[base] = 0.f;
    }
    int fidx = bid * 256 + t;
    if (fidx < NGB * NGJ * 32) flags[fidx] = 0u;
}

// fp32 -> fp16 conversion (vectorized; grid divides exactly)
__global__ void cvt_f16(const float* __restrict__ W, __half* __restrict__ Wt)
{
    int i = blockIdx.x * blockDim.x + threadIdx.x;   // float4 index
    float4 v = *(const float4*)(W + (size_t)i * 4);
    __half2 h0 = __floats2half2_rn(v.x, v.y);
    __half2 h1 = __floats2half2_rn(v.z, v.w);
    *(__half2*)(Wt + (size_t)i * 4)     = h0;
    *(__half2*)(Wt + (size_t)i * 4 + 2) = h1;
}

// ---------------------------------------------------------------------------
// Persistent recurrence = R15 + cp.async.cg staging + deduplicated barrier.
// Barrier: padded per-line flags, release store, backoff-free acquire spin
// (R15, proven). Staging: async copies, one wait, one sync.
// ---------------------------------------------------------------------------
__device__ __forceinline__ void groupbar(unsigned* gf, int gj, unsigned gen)
{
    __syncthreads();
    if (threadIdx.x == 0)
        asm volatile("st.release.gpu.u32 [%0], %1;"
                     :: "l"(gf + gj * 32), "r"(gen) : "memory");
    if (threadIdx.x < NGJ) {
        unsigned v;
        do {
            asm volatile("ld.acquire.gpu.u32 %0, [%1];"
                         : "=r"(v) : "l"(gf + threadIdx.x * 32) : "memory");
        } while (v < gen);
    }
    __syncthreads();
}

__device__ __forceinline__ void stageA(float* dst, const float* src)
{
#pragma unroll
    for (int q = 0; q < 8; q++) {
        int idx = threadIdx.x + q * 256;
        int row = idx >> 7;
        int col = (idx & 127) << 2;
        cpacg16(&dst[row * RSTR + col], src + row * D + col);
    }
}

__global__ __launch_bounds__(256, 1) void recurrence(
    const float* __restrict__ Wz, const float* __restrict__ Wr,
    const float* __restrict__ Wn,
    const float* __restrict__ bz, const float* __restrict__ br,
    const float* __restrict__ bn)
{
    extern __shared__ float sm[];
    float* sWU = sm;
    float* sWZ = sm + RS;
    float* sWR = sm + 2 * RS;
    float* sWN = sm + 3 * RS;
    float* sH1 = sm + 4 * RS;
    float* sH2 = sm + 5 * RS;

    const int tid = threadIdx.x;
    const int gb  = blockIdx.x & 3;
    const int gj  = blockIdx.x >> 2;
    const int b0  = gb * NB;
    const int j0  = gj * NJ;
    const int jl  = tid >> 4;
    const int bl  = tid & 15;
    const int b   = b0 + bl;
    const int j   = j0 + jl;
    unsigned* gf = g_flags + gb * NGJ * 32;

    const float* Genc = g_G;
    const float* Gdec = g_G + (size_t)M3 * 1536;

#pragma unroll
    for (int q = 0; q < 8; q++) {
        int idx = tid + q * 256;
        int row = idx >> 7;
        int col = (idx & 127) << 2;
        *(float4*)&sWU[row * RSTR + col] = *(const float4*)&g_Ut[(size_t)(j0 + row) * D + col];
        *(float4*)&sWZ[row * RSTR + col] = *(const float4*)&Wz[(size_t)(j0 + row) * D + col];
        *(float4*)&sWR[row * RSTR + col] = *(const float4*)&Wr[(size_t)(j0 + row) * D + col];
        *(float4*)&sWN[row * RSTR + col] = *(const float4*)&Wn[(size_t)(j0 + row) * D + col];
    }
    const float bzv = bz[j], brv = br[j], bnv = bn[j];
    const float* wu  = &sWU[jl * RSTR];
    const float* wz  = &sWZ[jl * RSTR];
    const float* wr  = &sWR[jl * RSTR];
    const float* wn  = &sWN[jl * RSTR];
    const float* h1r = &sH1[bl * RSTR];
    const float* h2r = &sH2[bl * RSTR];

    unsigned gen = 0;

    // phase 0: cell1(0) from h1(0)=0
    {
        const float* gc = Genc + (size_t)b * 1536;
        float z = 1.f / (1.f + __expf(-gc[j]));
        float n = tanhf(gc[1024 + j]);
        g_h1[(size_t)S + b * D + j] = z * n;
    }
    groupbar(gf, gj, ++gen);
    // groupbar's trailing __syncthreads protects sH1/sH2 reuse below

    // ---------------- encoder: fused {cell2(t), cell1(t+1)} ----------------
    for (int t = 0; t < TSRC; t++) {
        const int cur = t & 1, nxt = cur ^ 1;

        stageA(sH1, g_h1 + (size_t)nxt * S + b0 * D);
        stageA(sH2, g_h2 + (size_t)cur * S + b0 * D);
        asm volatile("cp.async.commit_group;");
        asm volatile("cp.async.wait_group 0;");
        __syncthreads();

        const int tc1 = (t + 1 < TSRC) ? t + 1 : TSRC - 1;
        const float* gc = Genc + (size_t)(tc1 * BB + b) * 1536;
        const float gz1 = gc[j], gr1 = gc[512 + j], gn1 = gc[1024 + j];

        unsigned long long aU1a = 0, aU1b = 0, aZa = 0, aZb = 0,
                           aRa = 0, aRb = 0, aNa = 0, aNb = 0,
                           aU2a = 0, aU2b = 0;
#pragma unroll 2
        for (int k = 0; k < D; k += 4) {
            unsigned long long h1a, h1b, h2a, h2b, ua, ub, za, zb, ra, rb, na, nb;
            LDSV2(h1r + k, h1a, h1b);
            LDSV2(h2r + k, h2a, h2b);
            LDSV2(wu + k, ua, ub);
            LDSV2(wz + k, za, zb);
            LDSV2(wr + k, ra, rb);
            LDSV2(wn + k, na, nb);
            FMA2(aU1a, h1a, ua); FMA2(aU1b, h1b, ub);
            FMA2(aZa,  h1a, za); FMA2(aZb,  h1b, zb);
            FMA2(aRa,  h1a, ra); FMA2(aRb,  h1b, rb);
            FMA2(aNa,  h1a, na); FMA2(aNb,  h1b, nb);
            FMA2(aU2a, h2a, ua); FMA2(aU2b, h2b, ub);
        }

        // cell2(t)
        {
            float dU = rsum2(aU2a, aU2b);
            float z = 1.f / (1.f + __expf(-(rsum2(aZa, aZb) + bzv + dU)));
            float r = 1.f / (1.f + __expf(-(rsum2(aRa, aRb) + brv + dU)));
            float n = tanhf(rsum2(aNa, aNb) + bnv + r * dU);
            float h = h2r[j];
            float hn = (1.f - z) * h + z * n;
            g_h2[(size_t)nxt * S + b * D + j] = hn;
            g_H[(size_t)t * S + b * D + j] = hn;
        }
        // cell1(t+1)
        if (t < TSRC - 1) {
            float hW = rsum2(aU1a, aU1b);
            float z = 1.f / (1.f + __expf(-(gz1 + hW)));
            float r = 1.f / (1.f + __expf(-(gr1 + hW)));
            float n = tanhf(gn1 + r * hW);
            float h = h1r[j];
            g_h1[(size_t)cur * S + b * D + j] = (1.f - z) * h + z * n;
        }
        groupbar(gf, gj, ++gen);
    }

    // ---------------- decoder (attention deferred) ----------------
    for (int t = 0; t < TTGT; t++) {
        const int cur = t & 1, nxt = cur ^ 1;

        stageA(sH2, g_h2 + (size_t)cur * S + b0 * D);
        asm volatile("cp.async.commit_group;");
        asm volatile("cp.async.wait_group 0;");
        __syncthreads();

        const float* gc = Gdec + (size_t)(t * BB + b) * 1536;
        const float gz = gc[j], gr = gc[512 + j], gn = gc[1024 + j];

        unsigned long long aA = 0, aB = 0;
#pragma unroll 4
        for (int k = 0; k < D; k += 4) {
            unsigned long long ha, hb, ua, ub;
            LDSV2(h2r + k, ha, hb);
            LDSV2(wu + k, ua, ub);
            FMA2(aA, ha, ua); FMA2(aB, hb, ub);
        }
        float hW = rsum2(aA, aB);
        float z = 1.f / (1.f + __expf(-(gz + hW)));
        float r = 1.f / (1.f + __expf(-(gr + hW)));
        float n = tanhf(gn + r * hW);
        float h = h2r[j];
        float hn = (1.f - z) * h + z * n;
        g_h2[(size_t)nxt * S + b * D + j] = hn;
        g_hall[(size_t)t * S + b * D + j] = hn;
        if (t < TTGT - 1) groupbar(gf, gj, ++gen);
    }
}

// ---------------------------------------------------------------------------
// Batched attention (unchanged, proven)
// ---------------------------------------------------------------------------
__global__ __launch_bounds__(256) void attn_batched(
    const int* __restrict__ src, float* __restrict__ ctx)
{
    const int b = blockIdx.x;
    const int tid = threadIdx.x;
    __shared__ float Hs[48][68];
    __shared__ float Qs[48][68];
    __shared__ float Sc[48][49];
    __shared__ float maskv[48];

    if (tid < TSRC) maskv[tid] = (src[tid * BB + b] == 0) ? 1.f : 0.f;

    const int ti = tid >> 4;
    const int tj = tid & 15;
    float acc[3][3] = {};

    for (int kc = 0; kc < 8; kc++) {
#pragma unroll
        for (int q = 0; q < 3; q++) {
            int idx = tid + q * 256;
            int row = idx >> 4;
            int col = (idx & 15) * 4;
            *(float4*)&Hs[row][col] =
                *(const float4*)&g_H[(size_t)row * S + b * D + kc * 64 + col];
            *(float4*)&Qs[row][col] =
                *(const float4*)&g_hall[(size_t)row * S + b * D + kc * 64 + col];
        }
        __syncthreads();
#pragma unroll 4
        for (int k = 0; k < 64; k += 4) {
            float4 q0 = *(const float4*)&Qs[3 * ti + 0][k];
            float4 q1 = *(const float4*)&Qs[3 * ti + 1][k];
            float4 q2 = *(const float4*)&Qs[3 * ti + 2][k];
            float4 h0 = *(const float4*)&Hs[3 * tj + 0][k];
            float4 h1 = *(const float4*)&Hs[3 * tj + 1][k];
            float4 h2 = *(const float4*)&Hs[3 * tj + 2][k];
#define DOT4A(A, B, Cv) \
            Cv = fmaf(A.x, B.x, Cv); Cv = fmaf(A.y, B.y, Cv); \
            Cv = fmaf(A.z, B.z, Cv); Cv = fmaf(A.w, B.w, Cv);
            DOT4A(q0, h0, acc[0][0]) DOT4A(q0, h1, acc[0][1]) DOT4A(q0, h2, acc[0][2])
            DOT4A(q1, h0, acc[1][0]) DOT4A(q1, h1, acc[1][1]) DOT4A(q1, h2, acc[1][2])
            DOT4A(q2, h0, acc[2][0]) DOT4A(q2, h1, acc[2][1]) DOT4A(q2, h2, acc[2][2])
#undef DOT4A
        }
        __syncthreads();
    }
#pragma unroll
    for (int i = 0; i < 3; i++)
#pragma unroll
        for (int jq = 0; jq < 3; jq++)
            Sc[3 * ti + i][3 * tj + jq] = acc[i][jq];
    __syncthreads();

    if (tid < TTGT) {
        const float scale = 0.044194173824159216f;
        float m = -1e30f;
        float sv[48];
#pragma unroll 8
        for (int jq = 0; jq < TSRC; jq++) {
            float s = (maskv[jq] != 0.f) ? -1e9f : Sc[tid][jq] * scale;
            sv[jq] = s;
            m = fmaxf(m, s);
        }
        float ssum = 0.f;
#pragma unroll 8
        for (int jq = 0; jq < TSRC; jq++) {
            float e = __expf(sv[jq] - m);
            sv[jq] = e;
            ssum += e;
        }
        float inv = 1.f / ssum;
#pragma unroll 8
        for (int jq = 0; jq < TSRC; jq++) Sc[tid][jq] = sv[jq] * inv;
    }
    __syncthreads();

    for (int kc = 0; kc < 8; kc++) {
#pragma unroll
        for (int q = 0; q < 3; q++) {
            int idx = tid + q * 256;
            int row = idx >> 4;
            int col = (idx & 15) * 4;
            *(float4*)&Hs[row][col] =
                *(const float4*)&g_H[(size_t)row * S + b * D + kc * 64 + col];
        }
        __syncthreads();
#pragma unroll
        for (int q = 0; q < 3; q++) {
            int idx = tid + q * 256;
            int i = idx >> 4;
            int d4 = (idx & 15) * 4;
            float4 cv = make_float4(0.f, 0.f, 0.f, 0.f);
#pragma unroll 8
            for (int jq = 0; jq < TSRC; jq++) {
                float a = Sc[i][jq];
                float4 hv = *(const float4*)&Hs[jq][d4];
                cv.x = fmaf(a, hv.x, cv.x); cv.y = fmaf(a, hv.y, cv.y);
                cv.z = fmaf(a, hv.z, cv.z); cv.w = fmaf(a, hv.w, cv.w);
            }
            *(float4*)&ctx[(size_t)i * S + b * D + kc * 64 + d4] = cv;
        }
        __syncthreads();
    }
}

// ---------------------------------------------------------------------------
extern "C" void kernel_launch(void* const* d_in, const int* in_sizes, int n_in,
                              void* d_out, int out_size)
{
    const int*   src  = (const int*)d_in[0];
    const int*   tgt  = (const int*)d_in[1];
    const float* U    = (const float*)d_in[2];
    const float* Wz   = (const float*)d_in[3];
    const float* bz   = (const float*)d_in[4];
    const float* Wr   = (const float*)d_in[5];
    const float* br   = (const float*)d_in[6];
    const float* Wn   = (const float*)d_in[7];
    const float* bn   = (const float*)d_in[8];
    const float* Een  = (const float*)d_in[9];
    const float* Ede  = (const float*)d_in[10];
    const float* Wout = (const float*)d_in[11];
    const float* Wctx = (const float*)d_in[12];
    float* out = (float*)d_out;

    float *pWcat, *pbcat, *pUt, *pG, *ph1, *ph2, *pctx, *phall;
    __half *pW16, *pA16;
    unsigned* pflags;
    cudaGetSymbolAddress((void**)&pWcat, g_Wcat);
    cudaGetSymbolAddress((void**)&pbcat, g_bcat);
    cudaGetSymbolAddress((void**)&pUt,   g_Ut);
    cudaGetSymbolAddress((void**)&pG,    g_G);
    cudaGetSymbolAddress((void**)&ph1,   g_h1);
    cudaGetSymbolAddress((void**)&ph2,   g_h2);
    cudaGetSymbolAddress((void**)&pctx,  g_ctx);
    cudaGetSymbolAddress((void**)&phall, g_hall);
    cudaGetSymbolAddress((void**)&pW16,  g_Wout16);
    cudaGetSymbolAddress((void**)&pA16,  g_A16);
    cudaGetSymbolAddress((void**)&pflags, g_flags);

    const int RECSMEM = 6 * RS * sizeof(float);              // 198,144 B
    cudaFuncSetAttribute(recurrence, cudaFuncAttributeMaxDynamicSharedMemorySize, RECSMEM);
    const int LOGSMEM = 6 * STW * sizeof(unsigned);          // 61,440 B
    cudaFuncSetAttribute(gemm_logits16, cudaFuncAttributeMaxDynamicSharedMemorySize, LOGSMEM);

    // 0: concat gate weights
    build_wcat<<<(1536 * D + 255) / 256, 256>>>(Wz, bz, Wr, br, Wn, bn);
    // 1: transpose U + zero state + clear flags
    prep<<<dim3(16, 16), dim3(32, 8)>>>(U, pUt, ph1, ph2, pflags);
    // 2: gate precompute for encoder AND decoder in one GEMM (M=6144)
    sgemm_tf32<<<dim3(12, 48), 256>>>(nullptr, src, Een, tgt, Ede, M3,
                                      pWcat, pbcat, nullptr, pG, nullptr,
                                      2 * M3, 1536, D);
    // 3: the whole sequential chain (cp.async staging + padded-flag barrier)
    recurrence<<<NGB * NGJ, 256, RECSMEM>>>(Wz, Wr, Wn, bz, br, bn);
    // 4: Wout -> fp16
    cvt_f16<<<(VDE * D / 4) / 256, 256>>>(Wout, pW16);
    // 5: all 48 attention steps, batched
    attn_batched<<<BB, 256>>>(src, pctx);
    // 6: out-projection, writes fp16 logits-A directly
    sgemm_tf32<<<dim3(4, 24), 256>>>(pctx, nullptr, nullptr, nullptr, nullptr, 0,
                                     Wctx, nullptr, phall, nullptr, pA16, M3, D, D);
    // 7: logits GEMM fp16 (BM=128, 3-stage, 2 CTAs/SM)
    gemm_logits16<<<dim3(250, 24), 256, LOGSMEM>>>(pA16, pW16, out);
}

// round 17
// speedup vs baseline: 1.0246x; 1.0246x over previous
#include <cuda_runtime.h>
#include <cuda_fp16.h>
#include <math.h>

// Problem constants
#define D    512
#define BB   64
#define TSRC 48
#define TTGT 48
#define VDE  32000
#define S    (BB * D)        // 32768 = one (B,D) state
#define M3   (TSRC * BB)     // 3072 rows

// encoder partition: 4 b-groups x 32 j-groups = 128 CTAs
#define NGB 4
#define NGJ 32
#define NB  16
#define NJ  16
#define RSTR 516
#define RS  (NB * RSTR)

// decoder partition: 16 b-groups x 8 j-groups = 128 CTAs
#define DNB 4      // batches per decoder CTA
#define DNJ 64     // columns per decoder CTA
#define DNG 8      // CTAs per decoder barrier group

// ---------------- scratch (device globals) -----------------------------------
__device__ float g_Wcat[1536 * D];
__device__ float g_bcat[1536];
__device__ float g_Ut[D * D];
__device__ float g_G[2 * M3 * 1536];     // [Genc ; Gdec] contiguous
__device__ float g_h1[2 * S];
__device__ float g_h2[2 * S];
__device__ float g_H[TSRC * S];
__device__ float g_hall[TTGT * S];
__device__ float g_ctx[TTGT * S];
__device__ __half g_Wout16[VDE * D];     // fp16 copy of W_out
__device__ __half g_A16[M3 * D];         // fp16 out = hall + ctx@Wctx^T
__device__ unsigned g_flags[NGB * NGJ * 32];   // encoder barrier (1 line/flag)
__device__ unsigned g_gbf[128 * 32];           // full-grid transition barrier
__device__ unsigned g_dfl[128 * 32];           // decoder barrier (16 groups x 8)

// ---------------------------------------------------------------------------
__device__ __forceinline__ float4 ldcg4(const float* p) {
    float4 v;
    asm volatile("ld.global.cg.v4.f32 {%0,%1,%2,%3}, [%4];"
                 : "=f"(v.x), "=f"(v.y), "=f"(v.z), "=f"(v.w) : "l"(p));
    return v;
}

__device__ __forceinline__ unsigned f2tf32(float x) {
    unsigned r;
    asm("cvt.rna.tf32.f32 %0, %1;" : "=r"(r) : "f"(x));
    return r;
}

__device__ __forceinline__ void cpasync16(void* sptr, const void* gptr) {
    unsigned s = (unsigned)__cvta_generic_to_shared(sptr);
    asm volatile("cp.async.ca.shared.global [%0], [%1], 16;" :: "r"(s), "l"(gptr));
}

// packed fp32x2 FMA (Blackwell) + paired smem loads (proven R9/R11)
#define LDSV2(p, lo, hi) do {                                                \
    unsigned _a = (unsigned)__cvta_generic_to_shared((const void*)(p));      \
    asm volatile("ld.shared.v2.u64 {%0,%1}, [%2];"                           \
                 : "=l"(lo), "=l"(hi) : "r"(_a)); } while (0)
#define FMA2(acc, a, b)                                                      \
    asm volatile("fma.rn.f32x2 %0, %1, %2, %0;" : "+l"(acc) : "l"(a), "l"(b))

__device__ __forceinline__ float rsum2(unsigned long long a, unsigned long long b) {
    float x0, x1, y0, y1;
    asm("mov.b64 {%0,%1}, %2;" : "=f"(x0), "=f"(x1) : "l"(a));
    asm("mov.b64 {%0,%1}, %2;" : "=f"(y0), "=f"(y1) : "l"(b));
    return (x0 + x1) + (y0 + y1);
}

// ---------------------------------------------------------------------------
// Generic tf32 NT GEMM (proven). Split id space for fused enc+dec gate GEMM.
// C16 != nullptr: write fp16 output instead of fp32 (feeds logits GEMM).
// ---------------------------------------------------------------------------
__global__ __launch_bounds__(256) void sgemm_tf32(
    const float* __restrict__ A, const int* __restrict__ ids,
    const float* __restrict__ E, const int* __restrict__ ids2,
    const float* __restrict__ E2, int Msplit,
    const float* __restrict__ Bm,
    const float* __restrict__ bias, const float* __restrict__ addend,
    float* __restrict__ C, __half* __restrict__ C16, int M, int N, int K)
{
    __shared__ unsigned As[128 * 36];
    __shared__ unsigned Bs[128 * 36];

    const int tid  = threadIdx.x;
    const int lane = tid & 31;
    const int warp = tid >> 5;
    const int row0 = blockIdx.y * 128;
    const int col0 = blockIdx.x * 128;

    const int mwarp = (warp >> 2) * 64;
    const int nwarp = (warp & 3) * 32;
    const int gid = lane >> 2;
    const int tig = lane & 3;

    const int lr = tid >> 3;
    const int lc = (tid & 7) * 4;

    const float* aPtr[4];
    const float* bPtr[4];
#pragma unroll
    for (int i = 0; i < 4; i++) {
        int r = row0 + lr + 32 * i;
        if (ids) {
            if (ids2 && r >= Msplit) aPtr[i] = E2 + (size_t)ids2[r - Msplit] * K;
            else                     aPtr[i] = E + (size_t)ids[r] * K;
        } else {
            aPtr[i] = A + (size_t)r * K;
        }
        bPtr[i] = Bm + (size_t)(col0 + lr + 32 * i) * K;
    }

    float acc[4][4][4];
#pragma unroll
    for (int mt = 0; mt < 4; mt++)
#pragma unroll
        for (int nt = 0; nt < 4; nt++)
#pragma unroll
            for (int q = 0; q < 4; q++) acc[mt][nt][q] = 0.f;

    const int kchunks = K >> 5;
    float4 aReg[4], bReg[4];
#pragma unroll
    for (int i = 0; i < 4; i++) {
        aReg[i] = *(const float4*)(aPtr[i] + lc);
        bReg[i] = *(const float4*)(bPtr[i] + lc);
    }

    for (int ch = 0; ch < kchunks; ch++) {
#pragma unroll
        for (int i = 0; i < 4; i++) {
            int base = (lr + 32 * i) * 36 + lc;
            uint4 av, bv;
            av.x = f2tf32(aReg[i].x); av.y = f2tf32(aReg[i].y);
            av.z = f2tf32(aReg[i].z); av.w = f2tf32(aReg[i].w);
            bv.x = f2tf32(bReg[i].x); bv.y = f2tf32(bReg[i].y);
            bv.z = f2tf32(bReg[i].z); bv.w = f2tf32(bReg[i].w);
            *(uint4*)&As[base] = av;
            *(uint4*)&Bs[base] = bv;
        }
        __syncthreads();

        if (ch + 1 < kchunks) {
            int koff = (ch + 1) * 32 + lc;
#pragma unroll
            for (int i = 0; i < 4; i++) {
                aReg[i] = *(const float4*)(aPtr[i] + koff);
                bReg[i] = *(const float4*)(bPtr[i] + koff);
            }
        }

#pragma unroll
        for (int ks = 0; ks < 4; ks++) {
            int k0 = ks * 8;
            unsigned bf[4][2];
#pragma unroll
            for (int nt = 0; nt < 4; nt++) {
                int nb = nwarp + nt * 8 + gid;
                bf[nt][0] = Bs[nb * 36 + k0 + tig];
                bf[nt][1] = Bs[nb * 36 + k0 + tig + 4];
            }
#pragma unroll
            for (int mt = 0; mt < 4; mt++) {
                int rm = mwarp + mt * 16 + gid;
                unsigned a0 = As[rm * 36 + k0 + tig];
                unsigned a1 = As[(rm + 8) * 36 + k0 + tig];
                unsigned a2 = As[rm * 36 + k0 + tig + 4];
                unsigned a3 = As[(rm + 8) * 36 + k0 + tig + 4];
#pragma unroll
                for (int nt = 0; nt < 4; nt++) {
                    asm volatile(
                        "mma.sync.aligned.m16n8k8.row.col.f32.tf32.tf32.f32 "
                        "{%0,%1,%2,%3}, {%4,%5,%6,%7}, {%8,%9}, {%0,%1,%2,%3};"
                        : "+f"(acc[mt][nt][0]), "+f"(acc[mt][nt][1]),
                          "+f"(acc[mt][nt][2]), "+f"(acc[mt][nt][3])
                        : "r"(a0), "r"(a1), "r"(a2), "r"(a3),
                          "r"(bf[nt][0]), "r"(bf[nt][1]));
                }
            }
        }
        __syncthreads();
    }

#pragma unroll
    for (int mt = 0; mt < 4; mt++) {
        int r = row0 + mwarp + mt * 16 + gid;
#pragma unroll
        for (int nt = 0; nt < 4; nt++) {
            int c = col0 + nwarp + nt * 8 + tig * 2;
            float v0 = acc[mt][nt][0], v1 = acc[mt][nt][1];
            float v2 = acc[mt][nt][2], v3 = acc[mt][nt][3];
            if (bias) {
                float b0 = bias[c], b1 = bias[c + 1];
                v0 += b0; v1 += b1; v2 += b0; v3 += b1;
            }
            if (addend) {
                float2 a0 = *(const float2*)&addend[(size_t)r * N + c];
                float2 a1 = *(const float2*)&addend[(size_t)(r + 8) * N + c];
                v0 += a0.x; v1 += a0.y; v2 += a1.x; v3 += a1.y;
            }
            if (C16) {
                *(__half2*)&C16[(size_t)r * N + c] = __floats2half2_rn(v0, v1);
                *(__half2*)&C16[(size_t)(r + 8) * N + c] = __floats2half2_rn(v2, v3);
            } else {
                float2 o0; o0.x = v0; o0.y = v1;
                float2 o1; o1.x = v2; o1.y = v3;
                *(float2*)&C[(size_t)r * N + c] = o0;
                *(float2*)&C[(size_t)(r + 8) * N + c] = o1;
            }
        }
    }
}

// ---------------------------------------------------------------------------
// Logits GEMM fp16 (R11, proven): BM=128, BN=128, BK=32 halfs, 256 threads,
// 3-stage cp.async, 2 CTAs/SM.
// ---------------------------------------------------------------------------
#define SAW 20                 // smem row stride in 32-bit words
#define STW (128 * SAW)        // words per matrix per stage (2560)

__global__ __launch_bounds__(256, 2) void gemm_logits16(
    const __half* __restrict__ A, const __half* __restrict__ B,
    float* __restrict__ C)
{
    extern __shared__ unsigned smL[];
    unsigned* AsW = smL;             // [3][STW]
    unsigned* BsW = smL + 3 * STW;   // [3][STW]

    const int tid  = threadIdx.x;
    const int lane = tid & 31;
    const int warp = tid >> 5;       // 0..7
    const int row0 = blockIdx.y * 128;
    const int col0 = blockIdx.x * 128;

    const int mwarp = (warp >> 2) * 64;
    const int nwarp = (warp & 3) * 32;
    const int gid = lane >> 2;
    const int tig = lane & 3;

    const int rL = tid >> 1;
    const int hL = (tid & 1) * 16;
    const __half* gA = A + (size_t)(row0 + rL) * D + hL;
    const __half* gB = B + (size_t)(col0 + rL) * D + hL;
    unsigned* dA = AsW + rL * SAW + (tid & 1) * 8;
    unsigned* dB = BsW + rL * SAW + (tid & 1) * 8;

#define LISSUE(ch, buf)                                                     \
    do {                                                                    \
        int ko = (ch) * 32;                                                 \
        cpasync16(dA + (buf) * STW + 0, gA + ko + 0);                       \
        cpasync16(dA + (buf) * STW + 4, gA + ko + 8);                       \
        cpasync16(dB + (buf) * STW + 0, gB + ko + 0);                       \
        cpasync16(dB + (buf) * STW + 4, gB + ko + 8);                       \
        asm volatile("cp.async.commit_group;");                             \
    } while (0)

    float acc[4][4][4];
#pragma unroll
    for (int mt = 0; mt < 4; mt++)
#pragma unroll
        for (int nt = 0; nt < 4; nt++)
#pragma unroll
            for (int q = 0; q < 4; q++) acc[mt][nt][q] = 0.f;

    LISSUE(0, 0);
    LISSUE(1, 1);
    LISSUE(2, 2);

    const int NCH = D / 32;   // 16
    for (int ch = 0; ch < NCH; ch++) {
        if      (ch <= NCH - 3) asm volatile("cp.async.wait_group 2;");
        else if (ch == NCH - 2) asm volatile("cp.async.wait_group 1;");
        else                    asm volatile("cp.async.wait_group 0;");
        __syncthreads();

        const int buf = ch % 3;
        const unsigned* Af = AsW + buf * STW;
        const unsigned* Bf = BsW + buf * STW;
#pragma unroll
        for (int ks = 0; ks < 2; ks++) {
            int kb = ks * 8;
            unsigned bf[4][2];
#pragma unroll
            for (int nt = 0; nt < 4; nt++) {
                int nb = nwarp + nt * 8 + gid;
                bf[nt][0] = Bf[nb * SAW + kb + tig];
                bf[nt][1] = Bf[nb * SAW + kb + tig + 4];
            }
#pragma unroll
            for (int mt = 0; mt < 4; mt++) {
                int rm = mwarp + mt * 16 + gid;
                unsigned a0 = Af[rm * SAW + kb + tig];
                unsigned a1 = Af[(rm + 8) * SAW + kb + tig];
                unsigned a2 = Af[rm * SAW + kb + tig + 4];
                unsigned a3 = Af[(rm + 8) * SAW + kb + tig + 4];
#pragma unroll
                for (int nt = 0; nt < 4; nt++) {
                    asm volatile(
                        "mma.sync.aligned.m16n8k16.row.col.f32.f16.f16.f32 "
                        "{%0,%1,%2,%3}, {%4,%5,%6,%7}, {%8,%9}, {%0,%1,%2,%3};"
                        : "+f"(acc[mt][nt][0]), "+f"(acc[mt][nt][1]),
                          "+f"(acc[mt][nt][2]), "+f"(acc[mt][nt][3])
                        : "r"(a0), "r"(a1), "r"(a2), "r"(a3),
                          "r"(bf[nt][0]), "r"(bf[nt][1]));
                }
            }
        }
        __syncthreads();
        if (ch + 3 < NCH) LISSUE(ch + 3, buf);
    }
#undef LISSUE

#pragma unroll
    for (int mt = 0; mt < 4; mt++) {
        size_t rr = (size_t)(row0 + mwarp + mt * 16 + gid);
#pragma unroll
        for (int nt = 0; nt < 4; nt++) {
            int c = col0 + nwarp + nt * 8 + tig * 2;
            float2 o0; o0.x = acc[mt][nt][0]; o0.y = acc[mt][nt][1];
            float2 o1; o1.x = acc[mt][nt][2]; o1.y = acc[mt][nt][3];
            *(float2*)&C[rr * VDE + c] = o0;
            *(float2*)&C[(rr + 8) * VDE + c] = o1;
        }
    }
}

// ---------------------------------------------------------------------------
__global__ void build_wcat(const float* __restrict__ Wz, const float* __restrict__ bz,
                           const float* __restrict__ Wr, const float* __restrict__ br,
                           const float* __restrict__ Wn, const float* __restrict__ bn)
{
    int idx = blockIdx.x * blockDim.x + threadIdx.x;
    if (idx >= 1536 * D) return;
    int j = idx / D, k = idx % D;
    int g = j >> 9, jr = j & 511;
    const float* W = (g == 0) ? Wz : (g == 1) ? Wr : Wn;
    g_Wcat[idx] = W[jr * D + k];
    if (k == 0) {
        const float* bvec = (g == 0) ? bz : (g == 1) ? br : bn;
        g_bcat[j] = bvec[jr];
    }
}

// transpose U + zero state + clear all flag arrays
__global__ void prep(const float* __restrict__ U, float* __restrict__ Ut,
                     float* __restrict__ h1, float* __restrict__ h2,
                     unsigned* __restrict__ f1, unsigned* __restrict__ f2,
                     unsigned* __restrict__ f3)
{
    __shared__ float tile[32][33];
    int k0 = blockIdx.y * 32;
    int j0 = blockIdx.x * 32;
    int tx = threadIdx.x, ty = threadIdx.y;
#pragma unroll
    for (int i = 0; i < 4; i++)
        tile[ty + i * 8][tx] = U[(size_t)(k0 + ty + i * 8) * D + j0 + tx];
    __syncthreads();
#pragma unroll
    for (int i = 0; i < 4; i++)
        Ut[(size_t)(j0 + ty + i * 8) * D + k0 + tx] = tile[tx][ty + i * 8];

    int bid = blockIdx.y * 16 + blockIdx.x;   // 0..255
    int t   = ty * 32 + tx;                   // 0..255
    if (t < 128) {
        int base = bid * 128 + t;
        h1[base] = 0.f;
        h2[base] = 0.f;
    }
    int fidx = bid * 256 + t;                 // 0..65535
    if (fidx < NGB * NGJ * 32) f1[fidx] = 0u;
    if (fidx < 128 * 32)       f2[fidx] = 0u;
    if (fidx < 128 * 32)       f3[fidx] = 0u;
}

// fp32 -> fp16 conversion (vectorized; grid divides exactly)
__global__ void cvt_f16(const float* __restrict__ W, __half* __restrict__ Wt)
{
    int i = blockIdx.x * blockDim.x + threadIdx.x;
    float4 v = *(const float4*)(W + (size_t)i * 4);
    __half2 h0 = __floats2half2_rn(v.x, v.y);
    __half2 h1 = __floats2half2_rn(v.z, v.w);
    *(__half2*)(Wt + (size_t)i * 4)     = h0;
    *(__half2*)(Wt + (size_t)i * 4 + 2) = h1;
}

// ---------------------------------------------------------------------------
// Persistent recurrence: encoder = R15 verbatim; decoder repartitioned to
// 16 b-groups x 8 j-groups (4 batches x 64 cols per CTA, barrier group = 8).
// ---------------------------------------------------------------------------
__device__ __forceinline__ void relflag(unsigned* p, unsigned gen)
{
    asm volatile("st.release.gpu.u32 [%0], %1;" :: "l"(p), "r"(gen) : "memory");
}
__device__ __forceinline__ unsigned acqflag(const unsigned* p)
{
    unsigned v;
    asm volatile("ld.acquire.gpu.u32 %0, [%1];" : "=r"(v) : "l"(p) : "memory");
    return v;
}

__device__ __forceinline__ void stageH(float* dst, const float* src)
{
#pragma unroll
    for (int q = 0; q < 8; q++) {
        int idx = threadIdx.x + q * 256;
        int row = idx >> 7;
        int col = (idx & 127) << 2;
        float4 v = ldcg4(src + row * D + col);
        *(float4*)&dst[row * RSTR + col] = v;
    }
}

__global__ __launch_bounds__(256, 1) void recurrence(
    const float* __restrict__ Wz, const float* __restrict__ Wr,
    const float* __restrict__ Wn,
    const float* __restrict__ bz, const float* __restrict__ br,
    const float* __restrict__ bn)
{
    extern __shared__ float sm[];
    float* sWU = sm;
    float* sWZ = sm + RS;
    float* sWR = sm + 2 * RS;
    float* sWN = sm + 3 * RS;
    float* sH1 = sm + 4 * RS;
    float* sH2 = sm + 5 * RS;

    const int tid = threadIdx.x;
    const int gb  = blockIdx.x & 3;
    const int gj  = blockIdx.x >> 2;
    const int b0  = gb * NB;
    const int j0  = gj * NJ;
    const int jl  = tid >> 4;
    const int bl  = tid & 15;
    const int b   = b0 + bl;
    const int j   = j0 + jl;
    unsigned* gf = g_flags + gb * NGJ * 32;

    const float* Genc = g_G;
    const float* Gdec = g_G + (size_t)M3 * 1536;

#pragma unroll
    for (int q = 0; q < 8; q++) {
        int idx = tid + q * 256;
        int row = idx >> 7;
        int col = (idx & 127) << 2;
        *(float4*)&sWU[row * RSTR + col] = *(const float4*)&g_Ut[(size_t)(j0 + row) * D + col];
        *(float4*)&sWZ[row * RSTR + col] = *(const float4*)&Wz[(size_t)(j0 + row) * D + col];
        *(float4*)&sWR[row * RSTR + col] = *(const float4*)&Wr[(size_t)(j0 + row) * D + col];
        *(float4*)&sWN[row * RSTR + col] = *(const float4*)&Wn[(size_t)(j0 + row) * D + col];
    }
    const float bzv = bz[j], brv = br[j], bnv = bn[j];
    const float* wu  = &sWU[jl * RSTR];
    const float* wz  = &sWZ[jl * RSTR];
    const float* wr  = &sWR[jl * RSTR];
    const float* wn  = &sWN[jl * RSTR];
    const float* h1r = &sH1[bl * RSTR];
    const float* h2r = &sH2[bl * RSTR];

    unsigned gen = 0;

    // phase 0: cell1(0) from h1(0)=0
    {
        const float* gc = Genc + (size_t)b * 1536;
        float z = 1.f / (1.f + __expf(-gc[j]));
        float n = tanhf(gc[1024 + j]);
        g_h1[(size_t)S + b * D + j] = z * n;
    }
    __syncthreads();
    if (tid == 0) relflag(gf + gj * 32, ++gen); else ++gen;
    if (tid < NGJ) { while (acqflag(gf + tid * 32) < gen) {} }
    __syncthreads();

    // ---------------- encoder: fused {cell2(t), cell1(t+1)} ----------------
    for (int t = 0; t < TSRC; t++) {
        const int cur = t & 1, nxt = cur ^ 1;

        __syncthreads();
        stageH(sH1, g_h1 + (size_t)nxt * S + b0 * D);
        stageH(sH2, g_h2 + (size_t)cur * S + b0 * D);
        __syncthreads();

        const int tc1 = (t + 1 < TSRC) ? t + 1 : TSRC - 1;
        const float* gc = Genc + (size_t)(tc1 * BB + b) * 1536;
        const float gz1 = gc[j], gr1 = gc[512 + j], gn1 = gc[1024 + j];

        unsigned long long aU1a = 0, aU1b = 0, aZa = 0, aZb = 0,
                           aRa = 0, aRb = 0, aNa = 0, aNb = 0,
                           aU2a = 0, aU2b = 0;
#pragma unroll 2
        for (int k = 0; k < D; k += 4) {
            unsigned long long h1a, h1b, h2a, h2b, ua, ub, za, zb, ra, rb, na, nb;
            LDSV2(h1r + k, h1a, h1b);
            LDSV2(h2r + k, h2a, h2b);
            LDSV2(wu + k, ua, ub);
            LDSV2(wz + k, za, zb);
            LDSV2(wr + k, ra, rb);
            LDSV2(wn + k, na, nb);
            FMA2(aU1a, h1a, ua); FMA2(aU1b, h1b, ub);
            FMA2(aZa,  h1a, za); FMA2(aZb,  h1b, zb);
            FMA2(aRa,  h1a, ra); FMA2(aRb,  h1b, rb);
            FMA2(aNa,  h1a, na); FMA2(aNb,  h1b, nb);
            FMA2(aU2a, h2a, ua); FMA2(aU2b, h2b, ub);
        }

        // cell2(t)
        {
            float dU = rsum2(aU2a, aU2b);
            float z = 1.f / (1.f + __expf(-(rsum2(aZa, aZb) + bzv + dU)));
            float r = 1.f / (1.f + __expf(-(rsum2(aRa, aRb) + brv + dU)));
            float n = tanhf(rsum2(aNa, aNb) + bnv + r * dU);
            float h = h2r[j];
            float hn = (1.f - z) * h + z * n;
            g_h2[(size_t)nxt * S + b * D + j] = hn;
            g_H[(size_t)t * S + b * D + j] = hn;
        }
        // cell1(t+1)
        if (t < TSRC - 1) {
            float hW = rsum2(aU1a, aU1b);
            float z = 1.f / (1.f + __expf(-(gz1 + hW)));
            float r = 1.f / (1.f + __expf(-(gr1 + hW)));
            float n = tanhf(gn1 + r * hW);
            float h = h1r[j];
            g_h1[(size_t)cur * S + b * D + j] = (1.f - z) * h + z * n;
        }
        __syncthreads();
        if (tid == 0) relflag(gf + gj * 32, ++gen); else ++gen;
        if (tid < NGJ) { while (acqflag(gf + tid * 32) < gen) {} }
        __syncthreads();
    }

    // ---- full-grid transition barrier (decoder repartitions batches) ----
    if (tid == 0) relflag(g_gbf + blockIdx.x * 32, 1u);
    if (tid < 128) { while (acqflag(g_gbf + tid * 32) < 1u) {} }
    __syncthreads();

    // ---------------- decoder: 16 b-groups x 8 j-groups ----------------
    // CTA: batches b0d..b0d+3, columns j0d..j0d+63. U rows in sm (stride 516),
    // h tile (4 x 512) staged per phase. Barrier group = 8 CTAs.
    const int dbg = blockIdx.x >> 3;           // 0..15
    const int djg = blockIdx.x & 7;            // 0..7
    const int b0d = dbg * DNB;
    const int j0d = djg * DNJ;
    const int jd  = tid >> 2;                  // 0..63 column
    const int bq  = tid & 3;                   // 0..3 batch
    const int jD  = j0d + jd;
    const int bD  = b0d + bq;
    unsigned* df = g_dfl + dbg * DNG * 32;

    float* sU  = sm;                           // 64 rows x stride 516
    float* sHd = sm + 4 * RS;                  // 4 rows x stride 516

    // load this CTA's 64 U rows (overwrites encoder weights; safe post-barrier)
#pragma unroll
    for (int q = 0; q < 32; q++) {
        int idx = tid + q * 256;               // 0..8191 float4 units
        int row = idx >> 7;                    // 0..63
        int col = (idx & 127) << 2;
        *(float4*)&sU[row * RSTR + col] = *(const float4*)&g_Ut[(size_t)(j0d + row) * D + col];
    }
    const float* wrow = &sU[jd * RSTR];
    const float* hrow = &sHd[bq * RSTR];
    unsigned dgen = 0;
    __syncthreads();

    for (int t = 0; t < TTGT; t++) {
        const int cur = t & 1, nxt = cur ^ 1;

        // stage h2[cur] for this CTA's 4 batches (full 512 cols)
#pragma unroll
        for (int q = 0; q < 2; q++) {
            int idx = tid + q * 256;           // 0..511 float4 units
            int row = idx >> 7;                // 0..3
            int col = (idx & 127) << 2;
            float4 v = ldcg4(g_h2 + (size_t)cur * S + (b0d + row) * D + col);
            *(float4*)&sHd[row * RSTR + col] = v;
        }
        __syncthreads();

        const float* gc = Gdec + (size_t)(t * BB + bD) * 1536;
        const float gz = gc[jD], gr = gc[512 + jD], gn = gc[1024 + jD];

        float a0 = 0.f, a1 = 0.f, a2 = 0.f, a3 = 0.f;
#pragma unroll 4
        for (int k = 0; k < D; k += 4) {
            float4 wv = *(const float4*)&wrow[k];
            float4 hv = *(const float4*)&hrow[k];
            a0 = fmaf(hv.x, wv.x, a0); a1 = fmaf(hv.y, wv.y, a1);
            a2 = fmaf(hv.z, wv.z, a2); a3 = fmaf(hv.w, wv.w, a3);
        }
        float hW = (a0 + a1) + (a2 + a3);
        float z = 1.f / (1.f + __expf(-(gz + hW)));
        float r = 1.f / (1.f + __expf(-(gr + hW)));
        float n = tanhf(gn + r * hW);
        float h = hrow[jD & 511];   // h2[bD][jD] lives at hrow[jD]
        float hn = (1.f - z) * h + z * n;
        g_h2[(size_t)nxt * S + bD * D + jD] = hn;
        g_hall[(size_t)t * S + bD * D + jD] = hn;

        if (t < TTGT - 1) {
            __syncthreads();
            if (tid == 0) relflag(df + djg * 32, ++dgen); else ++dgen;
            if (tid < DNG) { while (acqflag(df + tid * 32) < dgen) {} }
            __syncthreads();
        }
    }
}

// ---------------------------------------------------------------------------
// Batched attention (unchanged, proven)
// ---------------------------------------------------------------------------
__global__ __launch_bounds__(256) void attn_batched(
    const int* __restrict__ src, float* __restrict__ ctx)
{
    const int b = blockIdx.x;
    const int tid = threadIdx.x;
    __shared__ float Hs[48][68];
    __shared__ float Qs[48][68];
    __shared__ float Sc[48][49];
    __shared__ float maskv[48];

    if (tid < TSRC) maskv[tid] = (src[tid * BB + b] == 0) ? 1.f : 0.f;

    const int ti = tid >> 4;
    const int tj = tid & 15;
    float acc[3][3] = {};

    for (int kc = 0; kc < 8; kc++) {
#pragma unroll
        for (int q = 0; q < 3; q++) {
            int idx = tid + q * 256;
            int row = idx >> 4;
            int col = (idx & 15) * 4;
            *(float4*)&Hs[row][col] =
                *(const float4*)&g_H[(size_t)row * S + b * D + kc * 64 + col];
            *(float4*)&Qs[row][col] =
                *(const float4*)&g_hall[(size_t)row * S + b * D + kc * 64 + col];
        }
        __syncthreads();
#pragma unroll 4
        for (int k = 0; k < 64; k += 4) {
            float4 q0 = *(const float4*)&Qs[3 * ti + 0][k];
            float4 q1 = *(const float4*)&Qs[3 * ti + 1][k];
            float4 q2 = *(const float4*)&Qs[3 * ti + 2][k];
            float4 h0 = *(const float4*)&Hs[3 * tj + 0][k];
            float4 h1 = *(const float4*)&Hs[3 * tj + 1][k];
            float4 h2 = *(const float4*)&Hs[3 * tj + 2][k];
#define DOT4A(A, B, Cv) \
            Cv = fmaf(A.x, B.x, Cv); Cv = fmaf(A.y, B.y, Cv); \
            Cv = fmaf(A.z, B.z, Cv); Cv = fmaf(A.w, B.w, Cv);
            DOT4A(q0, h0, acc[0][0]) DOT4A(q0, h1, acc[0][1]) DOT4A(q0, h2, acc[0][2])
            DOT4A(q1, h0, acc[1][0]) DOT4A(q1, h1, acc[1][1]) DOT4A(q1, h2, acc[1][2])
            DOT4A(q2, h0, acc[2][0]) DOT4A(q2, h1, acc[2][1]) DOT4A(q2, h2, acc[2][2])
#undef DOT4A
        }
        __syncthreads();
    }
#pragma unroll
    for (int i = 0; i < 3; i++)
#pragma unroll
        for (int jq = 0; jq < 3; jq++)
            Sc[3 * ti + i][3 * tj + jq] = acc[i][jq];
    __syncthreads();

    if (tid < TTGT) {
        const float scale = 0.044194173824159216f;
        float m = -1e30f;
        float sv[48];
#pragma unroll 8
        for (int jq = 0; jq < TSRC; jq++) {
            float s = (maskv[jq] != 0.f) ? -1e9f : Sc[tid][jq] * scale;
            sv[jq] = s;
            m = fmaxf(m, s);
        }
        float ssum = 0.f;
#pragma unroll 8
        for (int jq = 0; jq < TSRC; jq++) {
            float e = __expf(sv[jq] - m);
            sv[jq] = e;
            ssum += e;
        }
        float inv = 1.f / ssum;
#pragma unroll 8
        for (int jq = 0; jq < TSRC; jq++) Sc[tid][jq] = sv[jq] * inv;
    }
    __syncthreads();

    for (int kc = 0; kc < 8; kc++) {
#pragma unroll
        for (int q = 0; q < 3; q++) {
            int idx = tid + q * 256;
            int row = idx >> 4;
            int col = (idx & 15) * 4;
            *(float4*)&Hs[row][col] =
                *(const float4*)&g_H[(size_t)row * S + b * D + kc * 64 + col];
        }
        __syncthreads();
#pragma unroll
        for (int q = 0; q < 3; q++) {
            int idx = tid + q * 256;
            int i = idx >> 4;
            int d4 = (idx & 15) * 4;
            float4 cv = make_float4(0.f, 0.f, 0.f, 0.f);
#pragma unroll 8
            for (int jq = 0; jq < TSRC; jq++) {
                float a = Sc[i][jq];
                float4 hv = *(const float4*)&Hs[jq][d4];
                cv.x = fmaf(a, hv.x, cv.x); cv.y = fmaf(a, hv.y, cv.y);
                cv.z = fmaf(a, hv.z, cv.z); cv.w = fmaf(a, hv.w, cv.w);
            }
            *(float4*)&ctx[(size_t)i * S + b * D + kc * 64 + d4] = cv;
        }
        __syncthreads();
    }
}

// ---------------------------------------------------------------------------
extern "C" void kernel_launch(void* const* d_in, const int* in_sizes, int n_in,
                              void* d_out, int out_size)
{
    const int*   src  = (const int*)d_in[0];
    const int*   tgt  = (const int*)d_in[1];
    const float* U    = (const float*)d_in[2];
    const float* Wz   = (const float*)d_in[3];
    const float* bz   = (const float*)d_in[4];
    const float* Wr   = (const float*)d_in[5];
    const float* br   = (const float*)d_in[6];
    const float* Wn   = (const float*)d_in[7];
    const float* bn   = (const float*)d_in[8];
    const float* Een  = (const float*)d_in[9];
    const float* Ede  = (const float*)d_in[10];
    const float* Wout = (const float*)d_in[11];
    const float* Wctx = (const float*)d_in[12];
    float* out = (float*)d_out;

    float *pWcat, *pbcat, *pUt, *pG, *ph1, *ph2, *pctx, *phall;
    __half *pW16, *pA16;
    unsigned *pf1, *pf2, *pf3;
    cudaGetSymbolAddress((void**)&pWcat, g_Wcat);
    cudaGetSymbolAddress((void**)&pbcat, g_bcat);
    cudaGetSymbolAddress((void**)&pUt,   g_Ut);
    cudaGetSymbolAddress((void**)&pG,    g_G);
    cudaGetSymbolAddress((void**)&ph1,   g_h1);
    cudaGetSymbolAddress((void**)&ph2,   g_h2);
    cudaGetSymbolAddress((void**)&pctx,  g_ctx);
    cudaGetSymbolAddress((void**)&phall, g_hall);
    cudaGetSymbolAddress((void**)&pW16,  g_Wout16);
    cudaGetSymbolAddress((void**)&pA16,  g_A16);
    cudaGetSymbolAddress((void**)&pf1,   g_flags);
    cudaGetSymbolAddress((void**)&pf2,   g_gbf);
    cudaGetSymbolAddress((void**)&pf3,   g_dfl);

    const int RECSMEM = 6 * RS * sizeof(float);              // 198,144 B
    cudaFuncSetAttribute(recurrence, cudaFuncAttributeMaxDynamicSharedMemorySize, RECSMEM);
    const int LOGSMEM = 6 * STW * sizeof(unsigned);          // 61,440 B
    cudaFuncSetAttribute(gemm_logits16, cudaFuncAttributeMaxDynamicSharedMemorySize, LOGSMEM);

    // 0: concat gate weights
    build_wcat<<<(1536 * D + 255) / 256, 256>>>(Wz, bz, Wr, br, Wn, bn);
    // 1: transpose U + zero state + clear all flags
    prep<<<dim3(16, 16), dim3(32, 8)>>>(U, pUt, ph1, ph2, pf1, pf2, pf3);
    // 2: gate precompute for encoder AND decoder in one GEMM (M=6144)
    sgemm_tf32<<<dim3(12, 48), 256>>>(nullptr, src, Een, tgt, Ede, M3,
                                      pWcat, pbcat, nullptr, pG, nullptr,
                                      2 * M3, 1536, D);
    // 3: the whole sequential chain (decoder barrier group = 8)
    recurrence<<<NGB * NGJ, 256, RECSMEM>>>(Wz, Wr, Wn, bz, br, bn);
    // 4: Wout -> fp16
    cvt_f16<<<(VDE * D / 4) / 256, 256>>>(Wout, pW16);
    // 5: all 48 attention steps, batched
    attn_batched<<<BB, 256>>>(src, pctx);
    // 6: out-projection, writes fp16 logits-A directly
    sgemm_tf32<<<dim3(4, 24), 256>>>(pctx, nullptr, nullptr, nullptr, nullptr, 0,
                                     Wctx, nullptr, phall, nullptr, pA16, M3, D, D);
    // 7: logits GEMM fp16 (BM=128, 3-stage, 2 CTAs/SM)
    gemm_logits16<<<dim3(250, 24), 256, LOGSMEM>>>(pA16, pW16, out);
}